// round 12
// baseline (speedup 1.0000x reference)
#include <cuda_runtime.h>
#include <cuda_bf16.h>
#include <cstdint>

#define L_NODES 100000
#define NSAMP   8

// Scratch (static __device__ arrays; no allocation allowed)
__device__ float g_H [(size_t)L_NODES * 128];
__device__ float g_AB[(size_t)L_NODES * 256];   // [A|B]
__device__ float g_E [(size_t)L_NODES * 128];

// ---------------------------------------------------------------------------
// bf16 helpers
// ---------------------------------------------------------------------------
__device__ __forceinline__ unsigned short bfh(float x) {
    return __bfloat16_as_ushort(__float2bfloat16(x));
}
__device__ __forceinline__ float bff(unsigned short u) {
    return __bfloat162float(__ushort_as_bfloat16(u));
}
__device__ __forceinline__ uint32_t pack2(unsigned short a, unsigned short b) {
    return (uint32_t)a | ((uint32_t)b << 16);
}

__device__ __forceinline__ void mma_bf16(float c[4], const uint32_t a[4],
                                         const uint32_t b[2]) {
    asm volatile(
        "mma.sync.aligned.m16n8k16.row.col.f32.bf16.bf16.f32 "
        "{%0,%1,%2,%3}, {%4,%5,%6,%7}, {%8,%9}, {%0,%1,%2,%3};"
        : "+f"(c[0]), "+f"(c[1]), "+f"(c[2]), "+f"(c[3])
        : "r"(a[0]), "r"(a[1]), "r"(a[2]), "r"(a[3]), "r"(b[0]), "r"(b[1]));
}

#define ASWZ(kp, r) ((r) ^ (((kp) & 3) << 3))

// ---------------------------------------------------------------------------
// Persistent tensor-core GEMM (3x bf16 hi/lo), N=128, 256 threads, 2 CTA/SM.
// C = op(Acat @ W + bias); optional fused final layer via Wf (writes outp).
// ---------------------------------------------------------------------------
__global__ __launch_bounds__(256, 2) void bgemm_bn128(
    const float* __restrict__ A1, const float* __restrict__ A2,
    int Ksplit, int K, int lda,
    const float* __restrict__ W,
    const float* __restrict__ bias,
    float* __restrict__ C, int ldc,
    int M, int do_relu, int ntiles,
    const float* __restrict__ Wf,     // 128x2, or null
    const float* __restrict__ bf2,
    float* __restrict__ outp)
{
    __shared__ uint32_t As_hi[8][128];
    __shared__ uint32_t As_lo[8][128];
    __shared__ uint32_t Ws_hi[8][136];
    __shared__ uint32_t Ws_lo[8][136];

    const int tid  = threadIdx.x;
    const int wid  = tid >> 5;
    const int lane = tid & 31;
    const int wm   = wid >> 1;
    const int wn   = wid & 1;
    const int t    = lane & 3;
    const int q    = lane >> 2;

    const int ar0 = tid >> 2;
    const int ar1 = (tid + 256) >> 2;
    const int akq = (tid & 3) << 2;
    const int wkp = tid >> 5;
    const int wnq = (tid & 31) << 2;
    const int nchunks = K >> 4;

    for (int tile = blockIdx.x; tile < ntiles; tile += gridDim.x) {
        const int mbase = tile * 128;

        float acc[2][8][4];
#pragma unroll
        for (int i = 0; i < 2; i++)
#pragma unroll
            for (int j = 0; j < 8; j++)
#pragma unroll
                for (int v = 0; v < 4; v++) acc[i][j][v] = 0.f;

        // prologue prefetch (chunk 0)
        float4 pa0, pa1, pw0, pw1;
        {
            const float* Aptr = (0 < Ksplit) ? A1 : A2;
            int kloc = (0 < Ksplit) ? 0 : -Ksplit;
            pa0 = make_float4(0.f, 0.f, 0.f, 0.f);
            pa1 = make_float4(0.f, 0.f, 0.f, 0.f);
            if (mbase + ar0 < M)
                pa0 = *(const float4*)(Aptr + (size_t)(mbase + ar0) * lda + kloc + akq);
            if (mbase + ar1 < M)
                pa1 = *(const float4*)(Aptr + (size_t)(mbase + ar1) * lda + kloc + akq);
            pw0 = *(const float4*)(W + (size_t)(2 * wkp)     * 128 + wnq);
            pw1 = *(const float4*)(W + (size_t)(2 * wkp + 1) * 128 + wnq);
        }

        for (int c = 0; c < nchunks; c++) {
            // convert prefetched regs -> smem
            {
                float4 v = pa0;
                unsigned short hx = bfh(v.x), hy = bfh(v.y), hz = bfh(v.z), hw = bfh(v.w);
                int p0 = akq >> 1, p1 = p0 + 1;
                As_hi[p0][ASWZ(p0, ar0)] = pack2(hx, hy);
                As_hi[p1][ASWZ(p1, ar0)] = pack2(hz, hw);
                As_lo[p0][ASWZ(p0, ar0)] = pack2(bfh(v.x - bff(hx)), bfh(v.y - bff(hy)));
                As_lo[p1][ASWZ(p1, ar0)] = pack2(bfh(v.z - bff(hz)), bfh(v.w - bff(hw)));
                v = pa1;
                hx = bfh(v.x); hy = bfh(v.y); hz = bfh(v.z); hw = bfh(v.w);
                As_hi[p0][ASWZ(p0, ar1)] = pack2(hx, hy);
                As_hi[p1][ASWZ(p1, ar1)] = pack2(hz, hw);
                As_lo[p0][ASWZ(p0, ar1)] = pack2(bfh(v.x - bff(hx)), bfh(v.y - bff(hy)));
                As_lo[p1][ASWZ(p1, ar1)] = pack2(bfh(v.z - bff(hz)), bfh(v.w - bff(hw)));
                const float* av = &pw0.x;
                const float* bv = &pw1.x;
#pragma unroll
                for (int j = 0; j < 4; j++) {
                    unsigned short ha = bfh(av[j]), hb = bfh(bv[j]);
                    Ws_hi[wkp][wnq + j] = pack2(ha, hb);
                    Ws_lo[wkp][wnq + j] = pack2(bfh(av[j] - bff(ha)), bfh(bv[j] - bff(hb)));
                }
            }
            __syncthreads();

            // prefetch next chunk
            if (c + 1 < nchunks) {
                int k0 = (c + 1) << 4;
                const float* Aptr = (k0 < Ksplit) ? A1 : A2;
                int kloc = (k0 < Ksplit) ? k0 : k0 - Ksplit;
                pa0 = make_float4(0.f, 0.f, 0.f, 0.f);
                pa1 = make_float4(0.f, 0.f, 0.f, 0.f);
                if (mbase + ar0 < M)
                    pa0 = *(const float4*)(Aptr + (size_t)(mbase + ar0) * lda + kloc + akq);
                if (mbase + ar1 < M)
                    pa1 = *(const float4*)(Aptr + (size_t)(mbase + ar1) * lda + kloc + akq);
                pw0 = *(const float4*)(W + (size_t)(k0 + 2 * wkp)     * 128 + wnq);
                pw1 = *(const float4*)(W + (size_t)(k0 + 2 * wkp + 1) * 128 + wnq);
            }

            // fragments + MMAs
            uint32_t ah[2][4], al[2][4];
#pragma unroll
            for (int mt = 0; mt < 2; mt++) {
                int row = wm * 32 + mt * 16 + q;
                int pa = t, pb = t + 4;
                ah[mt][0] = As_hi[pa][ASWZ(pa, row)];
                ah[mt][1] = As_hi[pa][ASWZ(pa, row + 8)];
                ah[mt][2] = As_hi[pb][ASWZ(pb, row)];
                ah[mt][3] = As_hi[pb][ASWZ(pb, row + 8)];
                al[mt][0] = As_lo[pa][ASWZ(pa, row)];
                al[mt][1] = As_lo[pa][ASWZ(pa, row + 8)];
                al[mt][2] = As_lo[pb][ASWZ(pb, row)];
                al[mt][3] = As_lo[pb][ASWZ(pb, row + 8)];
            }
#pragma unroll
            for (int g = 0; g < 2; g++) {
                uint32_t bh[4][2], bl[4][2];
#pragma unroll
                for (int j = 0; j < 4; j++) {
                    int col = wn * 64 + (g * 4 + j) * 8 + q;
                    bh[j][0] = Ws_hi[t][col];
                    bh[j][1] = Ws_hi[t + 4][col];
                    bl[j][0] = Ws_lo[t][col];
                    bl[j][1] = Ws_lo[t + 4][col];
                }
#pragma unroll
                for (int mt = 0; mt < 2; mt++)
#pragma unroll
                    for (int j = 0; j < 4; j++) {
                        float* cc = acc[mt][g * 4 + j];
                        mma_bf16(cc, ah[mt], bh[j]);
                        mma_bf16(cc, ah[mt], bl[j]);
                        mma_bf16(cc, al[mt], bh[j]);
                    }
            }
            __syncthreads();
        }

        if (!Wf) {
#pragma unroll
            for (int mt = 0; mt < 2; mt++) {
#pragma unroll
                for (int nt = 0; nt < 8; nt++) {
                    int row = mbase + wm * 32 + mt * 16 + q;
                    int col = wn * 64 + nt * 8 + 2 * t;
                    float b0 = bias ? bias[col]     : 0.f;
                    float b1 = bias ? bias[col + 1] : 0.f;
                    float v0 = acc[mt][nt][0] + b0;
                    float v1 = acc[mt][nt][1] + b1;
                    float v2 = acc[mt][nt][2] + b0;
                    float v3 = acc[mt][nt][3] + b1;
                    if (do_relu) {
                        v0 = fmaxf(v0, 0.f); v1 = fmaxf(v1, 0.f);
                        v2 = fmaxf(v2, 0.f); v3 = fmaxf(v3, 0.f);
                    }
                    if (row < M)
                        *(float2*)(C + (size_t)row * ldc + col) = make_float2(v0, v1);
                    if (row + 8 < M)
                        *(float2*)(C + (size_t)(row + 8) * ldc + col) = make_float2(v2, v3);
                }
            }
        } else {
            // fused final layer: out = relu(acc + bias) @ Wf + bf2
            __shared__ float red[2][128][2];
            float p[2][2][2];
#pragma unroll
            for (int mt = 0; mt < 2; mt++)
#pragma unroll
                for (int h = 0; h < 2; h++) { p[mt][h][0] = 0.f; p[mt][h][1] = 0.f; }

#pragma unroll
            for (int nt = 0; nt < 8; nt++) {
                int col = wn * 64 + nt * 8 + 2 * t;
                float b0 = bias ? bias[col]     : 0.f;
                float b1 = bias ? bias[col + 1] : 0.f;
                float w00 = Wf[col * 2 + 0], w01 = Wf[col * 2 + 1];
                float w10 = Wf[col * 2 + 2], w11 = Wf[col * 2 + 3];
#pragma unroll
                for (int mt = 0; mt < 2; mt++) {
                    float e0 = acc[mt][nt][0] + b0;
                    float e1 = acc[mt][nt][1] + b1;
                    float e2 = acc[mt][nt][2] + b0;
                    float e3 = acc[mt][nt][3] + b1;
                    if (do_relu) {
                        e0 = fmaxf(e0, 0.f); e1 = fmaxf(e1, 0.f);
                        e2 = fmaxf(e2, 0.f); e3 = fmaxf(e3, 0.f);
                    }
                    p[mt][0][0] = fmaf(e0, w00, fmaf(e1, w10, p[mt][0][0]));
                    p[mt][0][1] = fmaf(e0, w01, fmaf(e1, w11, p[mt][0][1]));
                    p[mt][1][0] = fmaf(e2, w00, fmaf(e3, w10, p[mt][1][0]));
                    p[mt][1][1] = fmaf(e2, w01, fmaf(e3, w11, p[mt][1][1]));
                }
            }
#pragma unroll
            for (int mt = 0; mt < 2; mt++)
#pragma unroll
                for (int h = 0; h < 2; h++)
#pragma unroll
                    for (int o = 0; o < 2; o++) {
                        float v = p[mt][h][o];
                        v += __shfl_xor_sync(0xffffffffu, v, 1);
                        v += __shfl_xor_sync(0xffffffffu, v, 2);
                        p[mt][h][o] = v;
                    }
            if (t == 0) {
#pragma unroll
                for (int mt = 0; mt < 2; mt++)
#pragma unroll
                    for (int h = 0; h < 2; h++) {
                        int row = wm * 32 + mt * 16 + q + h * 8;
                        red[wn][row][0] = p[mt][h][0];
                        red[wn][row][1] = p[mt][h][1];
                    }
            }
            __syncthreads();
            {
                int row = tid >> 1, o = tid & 1;
                int grow = mbase + row;
                if (grow < M)
                    outp[(size_t)grow * 2 + o] =
                        red[0][row][o] + red[1][row][o] + bf2[o];
            }
            __syncthreads();   // red safe for next tile
        }
    }
}

// ---------------------------------------------------------------------------
// Fused K2: AB[M x 256] = H @ [Wtop | Wbot]   (3x bf16 hi/lo, no bias/relu)
// 512 threads, 16 warps in 4(m) x 4(n); warp tile 32x64; block tile 128x256.
// A converted ONCE per chunk for both output halves. Persistent over tiles.
// W' (k,n): n<128 -> Wg[k][n], else Wg[128+k][n-128].
// ---------------------------------------------------------------------------
__global__ __launch_bounds__(512, 1) void bgemm_k2_bn256(
    const float* __restrict__ H, const float* __restrict__ Wg,
    float* __restrict__ AB, int M, int ntiles)
{
    __shared__ uint32_t As_hi[8][128];
    __shared__ uint32_t As_lo[8][128];
    __shared__ uint32_t Ws_hi[8][264];
    __shared__ uint32_t Ws_lo[8][264];

    const int tid  = threadIdx.x;
    const int wid  = tid >> 5;
    const int lane = tid & 31;
    const int wm   = wid >> 2;        // 0..3
    const int wn   = wid & 3;         // 0..3
    const int t    = lane & 3;
    const int q    = lane >> 2;

    // A load: 512 float4 slots, one per thread
    const int ar  = tid >> 2;                 // 0..127
    const int akq = (tid & 3) << 2;           // 0,4,8,12
    // W load: kp = 0..7, col-quad 0..63
    const int wkp = tid >> 6;                 // 0..7
    const int wnq = (tid & 63) << 2;          // 0..252
    const float* WB = (wnq < 128) ? (Wg + wnq)
                                  : (Wg + 128 * 128 + (wnq - 128));

    for (int tile = blockIdx.x; tile < ntiles; tile += gridDim.x) {
        const int mbase = tile * 128;

        float acc[2][8][4];
#pragma unroll
        for (int i = 0; i < 2; i++)
#pragma unroll
            for (int j = 0; j < 8; j++)
#pragma unroll
                for (int v = 0; v < 4; v++) acc[i][j][v] = 0.f;

        float4 pa, pw0, pw1;
        pa = make_float4(0.f, 0.f, 0.f, 0.f);
        if (mbase + ar < M)
            pa = *(const float4*)(H + (size_t)(mbase + ar) * 128 + akq);
        pw0 = *(const float4*)(WB + (size_t)(2 * wkp)     * 128);
        pw1 = *(const float4*)(WB + (size_t)(2 * wkp + 1) * 128);

#pragma unroll 1
        for (int c = 0; c < 8; c++) {
            // convert regs -> smem
            {
                float4 v = pa;
                unsigned short hx = bfh(v.x), hy = bfh(v.y), hz = bfh(v.z), hw = bfh(v.w);
                int p0 = akq >> 1, p1 = p0 + 1;
                As_hi[p0][ASWZ(p0, ar)] = pack2(hx, hy);
                As_hi[p1][ASWZ(p1, ar)] = pack2(hz, hw);
                As_lo[p0][ASWZ(p0, ar)] = pack2(bfh(v.x - bff(hx)), bfh(v.y - bff(hy)));
                As_lo[p1][ASWZ(p1, ar)] = pack2(bfh(v.z - bff(hz)), bfh(v.w - bff(hw)));
                const float* av = &pw0.x;
                const float* bv = &pw1.x;
#pragma unroll
                for (int j = 0; j < 4; j++) {
                    unsigned short ha = bfh(av[j]), hb = bfh(bv[j]);
                    Ws_hi[wkp][wnq + j] = pack2(ha, hb);
                    Ws_lo[wkp][wnq + j] = pack2(bfh(av[j] - bff(ha)), bfh(bv[j] - bff(hb)));
                }
            }
            __syncthreads();

            if (c + 1 < 8) {
                int k0 = (c + 1) << 4;
                pa = make_float4(0.f, 0.f, 0.f, 0.f);
                if (mbase + ar < M)
                    pa = *(const float4*)(H + (size_t)(mbase + ar) * 128 + k0 + akq);
                pw0 = *(const float4*)(WB + (size_t)(k0 + 2 * wkp)     * 128);
                pw1 = *(const float4*)(WB + (size_t)(k0 + 2 * wkp + 1) * 128);
            }

            uint32_t ah[2][4], al[2][4];
#pragma unroll
            for (int mt = 0; mt < 2; mt++) {
                int row = wm * 32 + mt * 16 + q;
                int pA = t, pB = t + 4;
                ah[mt][0] = As_hi[pA][ASWZ(pA, row)];
                ah[mt][1] = As_hi[pA][ASWZ(pA, row + 8)];
                ah[mt][2] = As_hi[pB][ASWZ(pB, row)];
                ah[mt][3] = As_hi[pB][ASWZ(pB, row + 8)];
                al[mt][0] = As_lo[pA][ASWZ(pA, row)];
                al[mt][1] = As_lo[pA][ASWZ(pA, row + 8)];
                al[mt][2] = As_lo[pB][ASWZ(pB, row)];
                al[mt][3] = As_lo[pB][ASWZ(pB, row + 8)];
            }
#pragma unroll
            for (int g = 0; g < 2; g++) {
                uint32_t bh[4][2], bl[4][2];
#pragma unroll
                for (int j = 0; j < 4; j++) {
                    int col = wn * 64 + (g * 4 + j) * 8 + q;
                    bh[j][0] = Ws_hi[t][col];
                    bh[j][1] = Ws_hi[t + 4][col];
                    bl[j][0] = Ws_lo[t][col];
                    bl[j][1] = Ws_lo[t + 4][col];
                }
#pragma unroll
                for (int mt = 0; mt < 2; mt++)
#pragma unroll
                    for (int j = 0; j < 4; j++) {
                        float* cc = acc[mt][g * 4 + j];
                        mma_bf16(cc, ah[mt], bh[j]);
                        mma_bf16(cc, ah[mt], bl[j]);
                        mma_bf16(cc, al[mt], bh[j]);
                    }
            }
            __syncthreads();
        }

        // epilogue: plain stores (no bias/relu), ldc = 256
#pragma unroll
        for (int mt = 0; mt < 2; mt++) {
#pragma unroll
            for (int nt = 0; nt < 8; nt++) {
                int row = mbase + wm * 32 + mt * 16 + q;
                int col = wn * 64 + nt * 8 + 2 * t;
                if (row < M)
                    *(float2*)(AB + (size_t)row * 256 + col) =
                        make_float2(acc[mt][nt][0], acc[mt][nt][1]);
                if (row + 8 < M)
                    *(float2*)(AB + (size_t)(row + 8) * 256 + col) =
                        make_float2(acc[mt][nt][2], acc[mt][nt][3]);
            }
        }
    }
}

// ---------------------------------------------------------------------------
// K3: E[l,:] = (1/S) * sum_s relu(A[idx0[s,l],:] + B[idx1[s,l],:] + b_g1)
// ---------------------------------------------------------------------------
__global__ __launch_bounds__(256) void gather_mean_kernel(
    const float4* __restrict__ AB,
    const int* __restrict__ idx0, const int* __restrict__ idx1,
    const float* __restrict__ bg,
    float4* __restrict__ E)
{
    int gw   = (blockIdx.x * blockDim.x + threadIdx.x) >> 5;
    int lane = threadIdx.x & 31;
    if (gw >= L_NODES) return;

    float4 bg4 = ((const float4*)bg)[lane];
    float4 acc = make_float4(0.f, 0.f, 0.f, 0.f);
#pragma unroll
    for (int s = 0; s < NSAMP; s++) {
        int i0 = idx0[s * L_NODES + gw];
        int i1 = idx1[s * L_NODES + gw];
        float4 a = AB[(size_t)i0 * 64 + lane];
        float4 b = AB[(size_t)i1 * 64 + 32 + lane];
        acc.x += fmaxf(a.x + b.x + bg4.x, 0.f);
        acc.y += fmaxf(a.y + b.y + bg4.y, 0.f);
        acc.z += fmaxf(a.z + b.z + bg4.z, 0.f);
        acc.w += fmaxf(a.w + b.w + bg4.w, 0.f);
    }
    const float inv = 1.0f / (float)NSAMP;
    E[(size_t)gw * 32 + lane] =
        make_float4(acc.x * inv, acc.y * inv, acc.z * inv, acc.w * inv);
}

extern "C" void kernel_launch(void* const* d_in, const int* in_sizes, int n_in,
                              void* d_out, int out_size)
{
    const float* X    = (const float*)d_in[0];
    const float* W_h1 = (const float*)d_in[1];
    const float* b_h1 = (const float*)d_in[2];
    const float* W_g1 = (const float*)d_in[3];   // (256, 128) row-major
    const float* b_g1 = (const float*)d_in[4];
    const float* W_f  = (const float*)d_in[5];
    const float* b_f  = (const float*)d_in[6];
    const int*   idx0 = (const int*)d_in[7];     // (8, 100000)
    const int*   idx1 = (const int*)d_in[8];
    float* out = (float*)d_out;

    float *H, *AB, *E;
    cudaGetSymbolAddress((void**)&H,  g_H);
    cudaGetSymbolAddress((void**)&AB, g_AB);
    cudaGetSymbolAddress((void**)&E,  g_E);

    const int NT = (L_NODES + 127) / 128;  // 782 row tiles
    const int GW = (L_NODES * 32) / 256;   // 12500 blocks

    // K1: H = relu(X @ W_h1 + b_h1)
    bgemm_bn128<<<296, 256>>>(X, X, 256, 256, 256, W_h1, b_h1, H, 128,
                              L_NODES, 1, NT, nullptr, nullptr, nullptr);
    // K2 fused: AB = H @ [Wtop | Wbot]
    bgemm_k2_bn256<<<148, 512>>>(H, W_g1, AB, L_NODES, NT);
    // K3: E = mean_s relu(A[idx0] + B[idx1] + b_g1)
    gather_mean_kernel<<<GW, 256>>>((const float4*)AB, idx0, idx1, b_g1, (float4*)E);
    // K4+K5 fused: out = relu([H|E] @ W_g1 + b_g1) @ W_f + b_f
    bgemm_bn128<<<296, 256>>>(H, E, 128, 256, 128, W_g1, b_g1, AB, 128,
                              L_NODES, 1, NT, W_f, b_f, out);
}

// round 13
// speedup vs baseline: 1.1732x; 1.1732x over previous
#include <cuda_runtime.h>
#include <cuda_bf16.h>
#include <cstdint>

#define L_NODES 100000
#define NSAMP   8

// ---------------------------------------------------------------------------
// Scratch (static __device__; uint4 for 16B alignment)
// ---------------------------------------------------------------------------
__device__ uint4  g_Hhi[(size_t)L_NODES * 16];   // bf16 hi plane, [row][64 kp words]
__device__ uint4  g_Hlo[(size_t)L_NODES * 16];
__device__ uint4  g_Ehi[(size_t)L_NODES * 16];
__device__ uint4  g_Elo[(size_t)L_NODES * 16];
__device__ float  g_AB [(size_t)L_NODES * 256];  // fp32 [A|B] for gather
__device__ uint4  g_WPh1h[4096], g_WPh1l[4096];  // Wh1 packed: [128 kp][128 n]
__device__ uint4  g_WPg1h[4096], g_WPg1l[4096];  // Wg1 packed

// ---------------------------------------------------------------------------
// bf16 helpers
// ---------------------------------------------------------------------------
__device__ __forceinline__ unsigned short bfh(float x) {
    return __bfloat16_as_ushort(__float2bfloat16(x));
}
__device__ __forceinline__ float bff(unsigned short u) {
    return __bfloat162float(__ushort_as_bfloat16(u));
}
__device__ __forceinline__ uint32_t pack2(unsigned short a, unsigned short b) {
    return (uint32_t)a | ((uint32_t)b << 16);
}
__device__ __forceinline__ void mma_bf16(float c[4], const uint32_t a[4],
                                         const uint32_t b[2]) {
    asm volatile(
        "mma.sync.aligned.m16n8k16.row.col.f32.bf16.bf16.f32 "
        "{%0,%1,%2,%3}, {%4,%5,%6,%7}, {%8,%9}, {%0,%1,%2,%3};"
        : "+f"(c[0]), "+f"(c[1]), "+f"(c[2]), "+f"(c[3])
        : "r"(a[0]), "r"(a[1]), "r"(a[2]), "r"(a[3]), "r"(b[0]), "r"(b[1]));
}

// ---------------------------------------------------------------------------
// Prep: pack weights to bf16 hi/lo planes, layout [kp][n] (kp = k/2)
// ---------------------------------------------------------------------------
__global__ __launch_bounds__(256) void prep_weights(
    const float* __restrict__ Wh1, const float* __restrict__ Wg1)
{
    int i = blockIdx.x * 256 + threadIdx.x;   // 0..16383
    int kp = i >> 7, n = i & 127;
    uint32_t* h1h = (uint32_t*)g_WPh1h; uint32_t* h1l = (uint32_t*)g_WPh1l;
    uint32_t* g1h = (uint32_t*)g_WPg1h; uint32_t* g1l = (uint32_t*)g_WPg1l;
    float a = Wh1[(2 * kp) * 128 + n], b = Wh1[(2 * kp + 1) * 128 + n];
    unsigned short ha = bfh(a), hb = bfh(b);
    h1h[i] = pack2(ha, hb);
    h1l[i] = pack2(bfh(a - bff(ha)), bfh(b - bff(hb)));
    a = Wg1[(2 * kp) * 128 + n]; b = Wg1[(2 * kp + 1) * 128 + n];
    ha = bfh(a); hb = bfh(b);
    g1h[i] = pack2(ha, hb);
    g1l[i] = pack2(bfh(a - bff(ha)), bfh(b - bff(hb)));
}

// ---------------------------------------------------------------------------
// Double-buffered bf16 3-term GEMM, N=128, 256 threads, 2 CTA/SM.
// packedA: A given as hi/lo uint32 planes [row][ldaw]; else fp32 (cvt in-kernel).
// Epilogue: Wf!=null -> fused final layer to outp; else Chi!=null -> packed
// hi/lo planes; else fp32 C.
// Smem A layout: As[buf][row][12] (kp 0..7 + pad), bank-proven conflict-free.
// ---------------------------------------------------------------------------
__global__ __launch_bounds__(256, 2) void bgemm(
    const uint32_t* __restrict__ A1hi, const uint32_t* __restrict__ A1lo,
    const uint32_t* __restrict__ A2hi, const uint32_t* __restrict__ A2lo,
    int Ksplit, int K, int ldaw, int packedA,
    const uint32_t* __restrict__ Whi, const uint32_t* __restrict__ Wlo,
    const float* __restrict__ bias,
    float* __restrict__ C, int ldc,
    uint32_t* __restrict__ Chi, uint32_t* __restrict__ Clo,
    int M, int do_relu,
    const float* __restrict__ Wf, const float* __restrict__ bf2,
    float* __restrict__ outp)
{
    __shared__ uint32_t As_hi[2][128][12];
    __shared__ uint32_t As_lo[2][128][12];
    __shared__ uint32_t Ws_hi[2][8][136];
    __shared__ uint32_t Ws_lo[2][8][136];

    const int tid  = threadIdx.x;
    const int wid  = tid >> 5;
    const int lane = tid & 31;
    const int wm   = wid >> 1;
    const int wn   = wid & 1;
    const int t    = lane & 3;
    const int q    = lane >> 2;
    const int mbase = blockIdx.x * 128;
    const int nchunks = K >> 4;

    // load geometry
    const int prow = tid >> 1, phalf = tid & 1;              // packed A
    const int fr0 = tid >> 2, fr1 = fr0 + 64;                // fp32 A rows
    const int fkq = (tid & 3) << 2;                          // fp32 k offset
    const int wkp = tid >> 5, wnq = (tid & 31) << 2;         // W

    float acc[2][8][4];
#pragma unroll
    for (int i = 0; i < 2; i++)
#pragma unroll
        for (int j = 0; j < 8; j++)
#pragma unroll
            for (int v = 0; v < 4; v++) acc[i][j][v] = 0.f;

    uint4 rAh, rAl, rWh, rWl;   // prefetch (fp32 path bit-casts floats into rAh/rAl)

#define LOAD_CHUNK(c)                                                          \
    do {                                                                       \
        if (packedA) {                                                         \
            int kw = (c) << 3;                                                 \
            const uint32_t *ph, *pl; int off;                                  \
            if ((kw << 1) < Ksplit) { ph = A1hi; pl = A1lo; off = kw; }        \
            else { ph = A2hi; pl = A2lo; off = kw - (Ksplit >> 1); }           \
            int grow = mbase + prow;                                           \
            rAh = make_uint4(0u,0u,0u,0u); rAl = make_uint4(0u,0u,0u,0u);      \
            if (grow < M) {                                                    \
                size_t o = (size_t)grow * ldaw + off + phalf * 4;              \
                rAh = *(const uint4*)(ph + o);                                 \
                rAl = *(const uint4*)(pl + o);                                 \
            }                                                                  \
        } else {                                                               \
            const float* Af = (const float*)A1hi;                              \
            int kk = (c) << 4;                                                 \
            rAh = make_uint4(0u,0u,0u,0u); rAl = make_uint4(0u,0u,0u,0u);      \
            if (mbase + fr0 < M)                                               \
                rAh = *(const uint4*)(Af + (size_t)(mbase + fr0) * ldaw + kk + fkq); \
            if (mbase + fr1 < M)                                               \
                rAl = *(const uint4*)(Af + (size_t)(mbase + fr1) * ldaw + kk + fkq); \
        }                                                                      \
        rWh = *(const uint4*)(Whi + (size_t)(((c) << 3) + wkp) * 128 + wnq);   \
        rWl = *(const uint4*)(Wlo + (size_t)(((c) << 3) + wkp) * 128 + wnq);   \
    } while (0)

#define STORE_CHUNK(b)                                                         \
    do {                                                                       \
        if (packedA) {                                                         \
            *(uint4*)&As_hi[b][prow][phalf * 4] = rAh;                         \
            *(uint4*)&As_lo[b][prow][phalf * 4] = rAl;                         \
        } else {                                                               \
            int p0 = fkq >> 1;                                                 \
            float x0 = __uint_as_float(rAh.x), x1 = __uint_as_float(rAh.y);    \
            float x2 = __uint_as_float(rAh.z), x3 = __uint_as_float(rAh.w);    \
            unsigned short h0 = bfh(x0), h1 = bfh(x1), h2 = bfh(x2), h3 = bfh(x3); \
            As_hi[b][fr0][p0]     = pack2(h0, h1);                             \
            As_hi[b][fr0][p0 + 1] = pack2(h2, h3);                             \
            As_lo[b][fr0][p0]     = pack2(bfh(x0 - bff(h0)), bfh(x1 - bff(h1))); \
            As_lo[b][fr0][p0 + 1] = pack2(bfh(x2 - bff(h2)), bfh(x3 - bff(h3))); \
            x0 = __uint_as_float(rAl.x); x1 = __uint_as_float(rAl.y);          \
            x2 = __uint_as_float(rAl.z); x3 = __uint_as_float(rAl.w);          \
            h0 = bfh(x0); h1 = bfh(x1); h2 = bfh(x2); h3 = bfh(x3);            \
            As_hi[b][fr1][p0]     = pack2(h0, h1);                             \
            As_hi[b][fr1][p0 + 1] = pack2(h2, h3);                             \
            As_lo[b][fr1][p0]     = pack2(bfh(x0 - bff(h0)), bfh(x1 - bff(h1))); \
            As_lo[b][fr1][p0 + 1] = pack2(bfh(x2 - bff(h2)), bfh(x3 - bff(h3))); \
        }                                                                      \
        *(uint4*)&Ws_hi[b][wkp][wnq] = rWh;                                    \
        *(uint4*)&Ws_lo[b][wkp][wnq] = rWl;                                    \
    } while (0)

    LOAD_CHUNK(0);
    STORE_CHUNK(0);
    __syncthreads();

    for (int c = 0; c < nchunks; c++) {
        const int b = c & 1;
        if (c + 1 < nchunks) LOAD_CHUNK(c + 1);

        // fragments from buf b
        uint32_t ah[2][4], al[2][4];
#pragma unroll
        for (int mt = 0; mt < 2; mt++) {
            int row = wm * 32 + mt * 16 + q;
            ah[mt][0] = As_hi[b][row][t];
            ah[mt][1] = As_hi[b][row + 8][t];
            ah[mt][2] = As_hi[b][row][t + 4];
            ah[mt][3] = As_hi[b][row + 8][t + 4];
            al[mt][0] = As_lo[b][row][t];
            al[mt][1] = As_lo[b][row + 8][t];
            al[mt][2] = As_lo[b][row][t + 4];
            al[mt][3] = As_lo[b][row + 8][t + 4];
        }
#pragma unroll
        for (int g = 0; g < 2; g++) {
            uint32_t bh[4][2], bl[4][2];
#pragma unroll
            for (int j = 0; j < 4; j++) {
                int col = wn * 64 + (g * 4 + j) * 8 + q;
                bh[j][0] = Ws_hi[b][t][col];
                bh[j][1] = Ws_hi[b][t + 4][col];
                bl[j][0] = Ws_lo[b][t][col];
                bl[j][1] = Ws_lo[b][t + 4][col];
            }
#pragma unroll
            for (int mt = 0; mt < 2; mt++)
#pragma unroll
                for (int j = 0; j < 4; j++) {
                    float* cc = acc[mt][g * 4 + j];
                    mma_bf16(cc, ah[mt], bh[j]);
                    mma_bf16(cc, ah[mt], bl[j]);
                    mma_bf16(cc, al[mt], bh[j]);
                }
        }

        if (c + 1 < nchunks) STORE_CHUNK(1 - b);
        __syncthreads();
    }

    if (Wf) {
        // fused final layer: out = relu(acc + bias) @ Wf + bf2
        __shared__ float red[2][128][2];
        float p[2][2][2];
#pragma unroll
        for (int mt = 0; mt < 2; mt++)
#pragma unroll
            for (int h = 0; h < 2; h++) { p[mt][h][0] = 0.f; p[mt][h][1] = 0.f; }
#pragma unroll
        for (int nt = 0; nt < 8; nt++) {
            int col = wn * 64 + nt * 8 + 2 * t;
            float b0 = bias ? bias[col]     : 0.f;
            float b1 = bias ? bias[col + 1] : 0.f;
            float w00 = Wf[col * 2 + 0], w01 = Wf[col * 2 + 1];
            float w10 = Wf[col * 2 + 2], w11 = Wf[col * 2 + 3];
#pragma unroll
            for (int mt = 0; mt < 2; mt++) {
                float e0 = acc[mt][nt][0] + b0;
                float e1 = acc[mt][nt][1] + b1;
                float e2 = acc[mt][nt][2] + b0;
                float e3 = acc[mt][nt][3] + b1;
                if (do_relu) {
                    e0 = fmaxf(e0, 0.f); e1 = fmaxf(e1, 0.f);
                    e2 = fmaxf(e2, 0.f); e3 = fmaxf(e3, 0.f);
                }
                p[mt][0][0] = fmaf(e0, w00, fmaf(e1, w10, p[mt][0][0]));
                p[mt][0][1] = fmaf(e0, w01, fmaf(e1, w11, p[mt][0][1]));
                p[mt][1][0] = fmaf(e2, w00, fmaf(e3, w10, p[mt][1][0]));
                p[mt][1][1] = fmaf(e2, w01, fmaf(e3, w11, p[mt][1][1]));
            }
        }
#pragma unroll
        for (int mt = 0; mt < 2; mt++)
#pragma unroll
            for (int h = 0; h < 2; h++)
#pragma unroll
                for (int o = 0; o < 2; o++) {
                    float v = p[mt][h][o];
                    v += __shfl_xor_sync(0xffffffffu, v, 1);
                    v += __shfl_xor_sync(0xffffffffu, v, 2);
                    p[mt][h][o] = v;
                }
        if (t == 0) {
#pragma unroll
            for (int mt = 0; mt < 2; mt++)
#pragma unroll
                for (int h = 0; h < 2; h++) {
                    int row = wm * 32 + mt * 16 + q + h * 8;
                    red[wn][row][0] = p[mt][h][0];
                    red[wn][row][1] = p[mt][h][1];
                }
        }
        __syncthreads();
        {
            int row = tid >> 1, o = tid & 1;
            int grow = mbase + row;
            if (grow < M)
                outp[(size_t)grow * 2 + o] = red[0][row][o] + red[1][row][o] + bf2[o];
        }
    } else if (Chi) {
        // packed hi/lo plane output (K1 -> H)
#pragma unroll
        for (int mt = 0; mt < 2; mt++) {
#pragma unroll
            for (int nt = 0; nt < 8; nt++) {
                int row = mbase + wm * 32 + mt * 16 + q;
                int col = wn * 64 + nt * 8 + 2 * t;
                float b0 = bias ? bias[col]     : 0.f;
                float b1 = bias ? bias[col + 1] : 0.f;
                float v0 = acc[mt][nt][0] + b0;
                float v1 = acc[mt][nt][1] + b1;
                float v2 = acc[mt][nt][2] + b0;
                float v3 = acc[mt][nt][3] + b1;
                if (do_relu) {
                    v0 = fmaxf(v0, 0.f); v1 = fmaxf(v1, 0.f);
                    v2 = fmaxf(v2, 0.f); v3 = fmaxf(v3, 0.f);
                }
                int w = col >> 1;
                if (row < M) {
                    unsigned short h0 = bfh(v0), h1 = bfh(v1);
                    Chi[(size_t)row * 64 + w] = pack2(h0, h1);
                    Clo[(size_t)row * 64 + w] =
                        pack2(bfh(v0 - bff(h0)), bfh(v1 - bff(h1)));
                }
                if (row + 8 < M) {
                    unsigned short h2 = bfh(v2), h3 = bfh(v3);
                    Chi[(size_t)(row + 8) * 64 + w] = pack2(h2, h3);
                    Clo[(size_t)(row + 8) * 64 + w] =
                        pack2(bfh(v2 - bff(h2)), bfh(v3 - bff(h3)));
                }
            }
        }
    } else {
        // fp32 output (K2a/K2b -> AB)
#pragma unroll
        for (int mt = 0; mt < 2; mt++) {
#pragma unroll
            for (int nt = 0; nt < 8; nt++) {
                int row = mbase + wm * 32 + mt * 16 + q;
                int col = wn * 64 + nt * 8 + 2 * t;
                float b0 = bias ? bias[col]     : 0.f;
                float b1 = bias ? bias[col + 1] : 0.f;
                float v0 = acc[mt][nt][0] + b0;
                float v1 = acc[mt][nt][1] + b1;
                float v2 = acc[mt][nt][2] + b0;
                float v3 = acc[mt][nt][3] + b1;
                if (do_relu) {
                    v0 = fmaxf(v0, 0.f); v1 = fmaxf(v1, 0.f);
                    v2 = fmaxf(v2, 0.f); v3 = fmaxf(v3, 0.f);
                }
                if (row < M)
                    *(float2*)(C + (size_t)row * ldc + col) = make_float2(v0, v1);
                if (row + 8 < M)
                    *(float2*)(C + (size_t)(row + 8) * ldc + col) = make_float2(v2, v3);
            }
        }
    }
#undef LOAD_CHUNK
#undef STORE_CHUNK
}

// ---------------------------------------------------------------------------
// K3: E = mean_s relu(A[idx0] + B[idx1] + b_g1); writes E as packed hi/lo.
// ---------------------------------------------------------------------------
__global__ __launch_bounds__(256) void gather_mean_kernel(
    const float4* __restrict__ AB,
    const int* __restrict__ idx0, const int* __restrict__ idx1,
    const float* __restrict__ bg,
    uint32_t* __restrict__ Ehi, uint32_t* __restrict__ Elo)
{
    int gw   = (blockIdx.x * blockDim.x + threadIdx.x) >> 5;
    int lane = threadIdx.x & 31;
    if (gw >= L_NODES) return;

    float4 bg4 = ((const float4*)bg)[lane];
    float4 acc = make_float4(0.f, 0.f, 0.f, 0.f);
#pragma unroll
    for (int s = 0; s < NSAMP; s++) {
        int i0 = idx0[s * L_NODES + gw];
        int i1 = idx1[s * L_NODES + gw];
        float4 a = AB[(size_t)i0 * 64 + lane];
        float4 b = AB[(size_t)i1 * 64 + 32 + lane];
        acc.x += fmaxf(a.x + b.x + bg4.x, 0.f);
        acc.y += fmaxf(a.y + b.y + bg4.y, 0.f);
        acc.z += fmaxf(a.z + b.z + bg4.z, 0.f);
        acc.w += fmaxf(a.w + b.w + bg4.w, 0.f);
    }
    const float inv = 1.0f / (float)NSAMP;
    float m0 = acc.x * inv, m1 = acc.y * inv, m2 = acc.z * inv, m3 = acc.w * inv;
    unsigned short h0 = bfh(m0), h1 = bfh(m1), h2 = bfh(m2), h3 = bfh(m3);
    size_t base = (size_t)gw * 64 + 2 * lane;
    *(uint2*)&Ehi[base] = make_uint2(pack2(h0, h1), pack2(h2, h3));
    *(uint2*)&Elo[base] = make_uint2(
        pack2(bfh(m0 - bff(h0)), bfh(m1 - bff(h1))),
        pack2(bfh(m2 - bff(h2)), bfh(m3 - bff(h3))));
}

extern "C" void kernel_launch(void* const* d_in, const int* in_sizes, int n_in,
                              void* d_out, int out_size)
{
    const float* X    = (const float*)d_in[0];
    const float* W_h1 = (const float*)d_in[1];
    const float* b_h1 = (const float*)d_in[2];
    const float* W_g1 = (const float*)d_in[3];   // (256, 128) row-major
    const float* b_g1 = (const float*)d_in[4];
    const float* W_f  = (const float*)d_in[5];
    const float* b_f  = (const float*)d_in[6];
    const int*   idx0 = (const int*)d_in[7];     // (8, 100000)
    const int*   idx1 = (const int*)d_in[8];
    float* out = (float*)d_out;

    uint32_t *Hhi, *Hlo, *Ehi, *Elo, *Wh1h, *Wh1l, *Wg1h, *Wg1l;
    float* AB;
    cudaGetSymbolAddress((void**)&Hhi, g_Hhi);
    cudaGetSymbolAddress((void**)&Hlo, g_Hlo);
    cudaGetSymbolAddress((void**)&Ehi, g_Ehi);
    cudaGetSymbolAddress((void**)&Elo, g_Elo);
    cudaGetSymbolAddress((void**)&AB,  g_AB);
    cudaGetSymbolAddress((void**)&Wh1h, g_WPh1h);
    cudaGetSymbolAddress((void**)&Wh1l, g_WPh1l);
    cudaGetSymbolAddress((void**)&Wg1h, g_WPg1h);
    cudaGetSymbolAddress((void**)&Wg1l, g_WPg1l);

    const int MT = (L_NODES + 127) / 128;  // 782 tiles
    const int GW = (L_NODES * 32) / 256;   // 12500 blocks

    // P: pack weights to bf16 hi/lo planes
    prep_weights<<<64, 256>>>(W_h1, W_g1);
    // K1: Hpacked = relu(X @ W_h1 + b_h1)   (fp32 A, packed C)
    bgemm<<<MT, 256>>>((const uint32_t*)X, nullptr, nullptr, nullptr,
                       256, 256, 256, 0, Wh1h, Wh1l, b_h1,
                       nullptr, 0, Hhi, Hlo, L_NODES, 1,
                       nullptr, nullptr, nullptr);
    // K2a: AB[:,0:128] = H @ Wtop           (packed A, fp32 C)
    bgemm<<<MT, 256>>>(Hhi, Hlo, nullptr, nullptr,
                       128, 128, 64, 1, Wg1h, Wg1l, nullptr,
                       AB, 256, nullptr, nullptr, L_NODES, 0,
                       nullptr, nullptr, nullptr);
    // K2b: AB[:,128:256] = H @ Wbot
    bgemm<<<MT, 256>>>(Hhi, Hlo, nullptr, nullptr,
                       128, 128, 64, 1, Wg1h + 64 * 128, Wg1l + 64 * 128, nullptr,
                       AB + 128, 256, nullptr, nullptr, L_NODES, 0,
                       nullptr, nullptr, nullptr);
    // K3: Epacked = mean_s relu(A[idx0] + B[idx1] + b_g1)
    gather_mean_kernel<<<GW, 256>>>((const float4*)AB, idx0, idx1, b_g1, Ehi, Elo);
    // K4+K5: out = relu([H|E] @ W_g1 + b_g1) @ W_f + b_f  (packed A, fused final)
    bgemm<<<MT, 256>>>(Hhi, Hlo, Ehi, Elo,
                       128, 256, 64, 1, Wg1h, Wg1l, b_g1,
                       nullptr, 0, nullptr, nullptr, L_NODES, 1,
                       W_f, b_f, out);
}

// round 16
// speedup vs baseline: 1.2709x; 1.0832x over previous
#include <cuda_runtime.h>
#include <cuda_bf16.h>
#include <cstdint>

#define L_NODES 100000
#define NSAMP   8

// ---------------------------------------------------------------------------
// Scratch (static __device__; uint4 for 16B alignment)
// ---------------------------------------------------------------------------
__device__ uint4  g_Hhi[(size_t)L_NODES * 16];   // bf16 hi plane, [row][64 kp words]
__device__ uint4  g_Hlo[(size_t)L_NODES * 16];
__device__ uint4  g_Ehi[(size_t)L_NODES * 16];
__device__ uint4  g_Elo[(size_t)L_NODES * 16];
__device__ float  g_AB [(size_t)L_NODES * 256];  // fp32 [A|B] for gather
__device__ uint4  g_WPh1h[4096], g_WPh1l[4096];  // Wh1 packed: [128 kp][128 n]
__device__ uint4  g_WPg1h[4096], g_WPg1l[4096];  // Wg1 packed

// ---------------------------------------------------------------------------
// helpers
// ---------------------------------------------------------------------------
__device__ __forceinline__ unsigned short bfh(float x) {
    return __bfloat16_as_ushort(__float2bfloat16(x));
}
__device__ __forceinline__ float bff(unsigned short u) {
    return __bfloat162float(__ushort_as_bfloat16(u));
}
__device__ __forceinline__ uint32_t pack2(unsigned short a, unsigned short b) {
    return (uint32_t)a | ((uint32_t)b << 16);
}
__device__ __forceinline__ void mma_bf16(float c[4], const uint32_t a[4],
                                         const uint32_t b[2]) {
    asm volatile(
        "mma.sync.aligned.m16n8k16.row.col.f32.bf16.bf16.f32 "
        "{%0,%1,%2,%3}, {%4,%5,%6,%7}, {%8,%9}, {%0,%1,%2,%3};"
        : "+f"(c[0]), "+f"(c[1]), "+f"(c[2]), "+f"(c[3])
        : "r"(a[0]), "r"(a[1]), "r"(a[2]), "r"(a[3]), "r"(b[0]), "r"(b[1]));
}
__device__ __forceinline__ void cp16(void* smem, const void* g, int pred) {
    uint32_t s = (uint32_t)__cvta_generic_to_shared(smem);
    int sz = pred ? 16 : 0;
    asm volatile("cp.async.cg.shared.global [%0], [%1], 16, %2;"
                 :: "r"(s), "l"(g), "r"(sz) : "memory");
}
#define CP_COMMIT() asm volatile("cp.async.commit_group;" ::: "memory")
#define CP_WAIT0()  asm volatile("cp.async.wait_group 0;" ::: "memory")

// ---------------------------------------------------------------------------
// Prep: pack weights to bf16 hi/lo planes, layout [kp][n] (kp = k/2)
// ---------------------------------------------------------------------------
__global__ __launch_bounds__(256) void prep_weights(
    const float* __restrict__ Wh1, const float* __restrict__ Wg1)
{
    int i = blockIdx.x * 256 + threadIdx.x;   // 0..16383
    int kp = i >> 7, n = i & 127;
    uint32_t* h1h = (uint32_t*)g_WPh1h; uint32_t* h1l = (uint32_t*)g_WPh1l;
    uint32_t* g1h = (uint32_t*)g_WPg1h; uint32_t* g1l = (uint32_t*)g_WPg1l;
    float a = Wh1[(2 * kp) * 128 + n], b = Wh1[(2 * kp + 1) * 128 + n];
    unsigned short ha = bfh(a), hb = bfh(b);
    h1h[i] = pack2(ha, hb);
    h1l[i] = pack2(bfh(a - bff(ha)), bfh(b - bff(hb)));
    a = Wg1[(2 * kp) * 128 + n]; b = Wg1[(2 * kp + 1) * 128 + n];
    ha = bfh(a); hb = bfh(b);
    g1h[i] = pack2(ha, hb);
    g1l[i] = pack2(bfh(a - bff(ha)), bfh(b - bff(hb)));
}

// ---------------------------------------------------------------------------
// K1 GEMM (fp32 A -> convert in-kernel, packed hi/lo C). R13-proven path.
// ---------------------------------------------------------------------------
__global__ __launch_bounds__(256, 2) void bgemm_f32(
    const float* __restrict__ Af, int K, int lda,
    const uint32_t* __restrict__ Whi, const uint32_t* __restrict__ Wlo,
    const float* __restrict__ bias,
    uint32_t* __restrict__ Chi, uint32_t* __restrict__ Clo,
    int M, int do_relu)
{
    __shared__ uint32_t As_hi[2][128][12];
    __shared__ uint32_t As_lo[2][128][12];
    __shared__ uint32_t Ws_hi[2][8][136];
    __shared__ uint32_t Ws_lo[2][8][136];

    const int tid  = threadIdx.x;
    const int wid  = tid >> 5;
    const int lane = tid & 31;
    const int wm   = wid >> 1;
    const int wn   = wid & 1;
    const int t    = lane & 3;
    const int q    = lane >> 2;
    const int mbase = blockIdx.x * 128;
    const int nchunks = K >> 4;

    const int fr0 = tid >> 2, fr1 = fr0 + 64;
    const int fkq = (tid & 3) << 2;
    const int wkp = tid >> 5, wnq = (tid & 31) << 2;

    float acc[2][8][4];
#pragma unroll
    for (int i = 0; i < 2; i++)
#pragma unroll
        for (int j = 0; j < 8; j++)
#pragma unroll
            for (int v = 0; v < 4; v++) acc[i][j][v] = 0.f;

    float4 rA0, rA1;
    uint4  rWh, rWl;

#define K1_LOAD(c)                                                             \
    do {                                                                       \
        int kk = (c) << 4;                                                     \
        rA0 = make_float4(0.f, 0.f, 0.f, 0.f);                                 \
        rA1 = make_float4(0.f, 0.f, 0.f, 0.f);                                 \
        if (mbase + fr0 < M)                                                   \
            rA0 = *(const float4*)(Af + (size_t)(mbase + fr0) * lda + kk + fkq); \
        if (mbase + fr1 < M)                                                   \
            rA1 = *(const float4*)(Af + (size_t)(mbase + fr1) * lda + kk + fkq); \
        rWh = *(const uint4*)(Whi + (size_t)(((c) << 3) + wkp) * 128 + wnq);   \
        rWl = *(const uint4*)(Wlo + (size_t)(((c) << 3) + wkp) * 128 + wnq);   \
    } while (0)

#define K1_STORE(b)                                                            \
    do {                                                                       \
        int p0 = fkq >> 1;                                                     \
        unsigned short h0 = bfh(rA0.x), h1 = bfh(rA0.y),                       \
                       h2 = bfh(rA0.z), h3 = bfh(rA0.w);                       \
        As_hi[b][fr0][p0]     = pack2(h0, h1);                                 \
        As_hi[b][fr0][p0 + 1] = pack2(h2, h3);                                 \
        As_lo[b][fr0][p0]     = pack2(bfh(rA0.x - bff(h0)), bfh(rA0.y - bff(h1))); \
        As_lo[b][fr0][p0 + 1] = pack2(bfh(rA0.z - bff(h2)), bfh(rA0.w - bff(h3))); \
        h0 = bfh(rA1.x); h1 = bfh(rA1.y); h2 = bfh(rA1.z); h3 = bfh(rA1.w);    \
        As_hi[b][fr1][p0]     = pack2(h0, h1);                                 \
        As_hi[b][fr1][p0 + 1] = pack2(h2, h3);                                 \
        As_lo[b][fr1][p0]     = pack2(bfh(rA1.x - bff(h0)), bfh(rA1.y - bff(h1))); \
        As_lo[b][fr1][p0 + 1] = pack2(bfh(rA1.z - bff(h2)), bfh(rA1.w - bff(h3))); \
        *(uint4*)&Ws_hi[b][wkp][wnq] = rWh;                                    \
        *(uint4*)&Ws_lo[b][wkp][wnq] = rWl;                                    \
    } while (0)

    K1_LOAD(0);
    K1_STORE(0);
    __syncthreads();

    for (int c = 0; c < nchunks; c++) {
        const int b = c & 1;
        if (c + 1 < nchunks) K1_LOAD(c + 1);

        uint32_t ah[2][4], al[2][4];
#pragma unroll
        for (int mt = 0; mt < 2; mt++) {
            int row = wm * 32 + mt * 16 + q;
            ah[mt][0] = As_hi[b][row][t];
            ah[mt][1] = As_hi[b][row + 8][t];
            ah[mt][2] = As_hi[b][row][t + 4];
            ah[mt][3] = As_hi[b][row + 8][t + 4];
            al[mt][0] = As_lo[b][row][t];
            al[mt][1] = As_lo[b][row + 8][t];
            al[mt][2] = As_lo[b][row][t + 4];
            al[mt][3] = As_lo[b][row + 8][t + 4];
        }
#pragma unroll
        for (int g = 0; g < 2; g++) {
            uint32_t bh[4][2], bl[4][2];
#pragma unroll
            for (int j = 0; j < 4; j++) {
                int col = wn * 64 + (g * 4 + j) * 8 + q;
                bh[j][0] = Ws_hi[b][t][col];
                bh[j][1] = Ws_hi[b][t + 4][col];
                bl[j][0] = Ws_lo[b][t][col];
                bl[j][1] = Ws_lo[b][t + 4][col];
            }
#pragma unroll
            for (int mt = 0; mt < 2; mt++)
#pragma unroll
                for (int j = 0; j < 4; j++) {
                    float* cc = acc[mt][g * 4 + j];
                    mma_bf16(cc, ah[mt], bh[j]);
                    mma_bf16(cc, ah[mt], bl[j]);
                    mma_bf16(cc, al[mt], bh[j]);
                }
        }

        if (c + 1 < nchunks) K1_STORE(1 - b);
        __syncthreads();
    }

    // packed hi/lo plane output
#pragma unroll
    for (int mt = 0; mt < 2; mt++) {
#pragma unroll
        for (int nt = 0; nt < 8; nt++) {
            int row = mbase + wm * 32 + mt * 16 + q;
            int col = wn * 64 + nt * 8 + 2 * t;
            float b0 = bias[col], b1 = bias[col + 1];
            float v0 = acc[mt][nt][0] + b0;
            float v1 = acc[mt][nt][1] + b1;
            float v2 = acc[mt][nt][2] + b0;
            float v3 = acc[mt][nt][3] + b1;
            if (do_relu) {
                v0 = fmaxf(v0, 0.f); v1 = fmaxf(v1, 0.f);
                v2 = fmaxf(v2, 0.f); v3 = fmaxf(v3, 0.f);
            }
            int w = col >> 1;
            if (row < M) {
                unsigned short h0 = bfh(v0), h1 = bfh(v1);
                Chi[(size_t)row * 64 + w] = pack2(h0, h1);
                Clo[(size_t)row * 64 + w] = pack2(bfh(v0 - bff(h0)), bfh(v1 - bff(h1)));
            }
            if (row + 8 < M) {
                unsigned short h2 = bfh(v2), h3 = bfh(v3);
                Chi[(size_t)(row + 8) * 64 + w] = pack2(h2, h3);
                Clo[(size_t)(row + 8) * 64 + w] = pack2(bfh(v2 - bff(h2)), bfh(v3 - bff(h3)));
            }
        }
    }
#undef K1_LOAD
#undef K1_STORE
}

// ---------------------------------------------------------------------------
// Packed-A GEMM with cp.async 2-stage pipeline (no register staging).
// Epilogue: Wf!=null -> fused final layer to outp; else fp32 C.
// ---------------------------------------------------------------------------
__global__ __launch_bounds__(256, 2) void bgemm_pk(
    const uint32_t* __restrict__ A1hi, const uint32_t* __restrict__ A1lo,
    const uint32_t* __restrict__ A2hi, const uint32_t* __restrict__ A2lo,
    int Ksplit, int K, int ldaw,
    const uint32_t* __restrict__ Whi, const uint32_t* __restrict__ Wlo,
    const float* __restrict__ bias,
    float* __restrict__ C, int ldc, int M, int do_relu,
    const float* __restrict__ Wf, const float* __restrict__ bf2,
    float* __restrict__ outp)
{
    __shared__ uint32_t As_hi[2][128][12];
    __shared__ uint32_t As_lo[2][128][12];
    __shared__ uint32_t Ws_hi[2][8][136];
    __shared__ uint32_t Ws_lo[2][8][136];

    const int tid  = threadIdx.x;
    const int wid  = tid >> 5;
    const int lane = tid & 31;
    const int wm   = wid >> 1;
    const int wn   = wid & 1;
    const int t    = lane & 3;
    const int q    = lane >> 2;
    const int mbase = blockIdx.x * 128;
    const int nchunks = K >> 4;

    const int prow = tid >> 1, phalf = tid & 1;
    const int wkp = tid >> 5, wnq = (tid & 31) << 2;

    float acc[2][8][4];
#pragma unroll
    for (int i = 0; i < 2; i++)
#pragma unroll
        for (int j = 0; j < 8; j++)
#pragma unroll
            for (int v = 0; v < 4; v++) acc[i][j][v] = 0.f;

#define PK_ISSUE(c, b)                                                         \
    do {                                                                       \
        int kw = (c) << 3;                                                     \
        const uint32_t *ph, *pl; int off;                                      \
        if ((kw << 1) < Ksplit) { ph = A1hi; pl = A1lo; off = kw; }            \
        else { ph = A2hi; pl = A2lo; off = kw - (Ksplit >> 1); }               \
        int grow = mbase + prow;                                               \
        int p = grow < M;                                                      \
        size_t o = (size_t)(p ? grow : 0) * ldaw + off + phalf * 4;            \
        cp16(&As_hi[b][prow][phalf * 4], ph + o, p);                           \
        cp16(&As_lo[b][prow][phalf * 4], pl + o, p);                           \
        size_t wo = (size_t)(kw + wkp) * 128 + wnq;                            \
        cp16(&Ws_hi[b][wkp][wnq], Whi + wo, 1);                                \
        cp16(&Ws_lo[b][wkp][wnq], Wlo + wo, 1);                                \
    } while (0)

    PK_ISSUE(0, 0);
    CP_COMMIT();

    for (int c = 0; c < nchunks; c++) {
        const int b = c & 1;
        CP_WAIT0();
        __syncthreads();               // chunk c visible; all warps done with c-1
        if (c + 1 < nchunks) {
            PK_ISSUE(c + 1, 1 - b);    // overlaps the MMA block below
            CP_COMMIT();
        }

        uint32_t ah[2][4], al[2][4];
#pragma unroll
        for (int mt = 0; mt < 2; mt++) {
            int row = wm * 32 + mt * 16 + q;
            ah[mt][0] = As_hi[b][row][t];
            ah[mt][1] = As_hi[b][row + 8][t];
            ah[mt][2] = As_hi[b][row][t + 4];
            ah[mt][3] = As_hi[b][row + 8][t + 4];
            al[mt][0] = As_lo[b][row][t];
            al[mt][1] = As_lo[b][row + 8][t];
            al[mt][2] = As_lo[b][row][t + 4];
            al[mt][3] = As_lo[b][row + 8][t + 4];
        }
#pragma unroll
        for (int g = 0; g < 2; g++) {
            uint32_t bh[4][2], bl[4][2];
#pragma unroll
            for (int j = 0; j < 4; j++) {
                int col = wn * 64 + (g * 4 + j) * 8 + q;
                bh[j][0] = Ws_hi[b][t][col];
                bh[j][1] = Ws_hi[b][t + 4][col];
                bl[j][0] = Ws_lo[b][t][col];
                bl[j][1] = Ws_lo[b][t + 4][col];
            }
#pragma unroll
            for (int mt = 0; mt < 2; mt++)
#pragma unroll
                for (int j = 0; j < 4; j++) {
                    float* cc = acc[mt][g * 4 + j];
                    mma_bf16(cc, ah[mt], bh[j]);
                    mma_bf16(cc, ah[mt], bl[j]);
                    mma_bf16(cc, al[mt], bh[j]);
                }
        }
    }

    if (Wf) {
        // fused final layer: out = relu(acc + bias) @ Wf + bf2
        __shared__ float red[2][128][2];
        float p[2][2][2];
#pragma unroll
        for (int mt = 0; mt < 2; mt++)
#pragma unroll
            for (int h = 0; h < 2; h++) { p[mt][h][0] = 0.f; p[mt][h][1] = 0.f; }
#pragma unroll
        for (int nt = 0; nt < 8; nt++) {
            int col = wn * 64 + nt * 8 + 2 * t;
            float b0 = bias ? bias[col]     : 0.f;
            float b1 = bias ? bias[col + 1] : 0.f;
            float w00 = Wf[col * 2 + 0], w01 = Wf[col * 2 + 1];
            float w10 = Wf[col * 2 + 2], w11 = Wf[col * 2 + 3];
#pragma unroll
            for (int mt = 0; mt < 2; mt++) {
                float e0 = acc[mt][nt][0] + b0;
                float e1 = acc[mt][nt][1] + b1;
                float e2 = acc[mt][nt][2] + b0;
                float e3 = acc[mt][nt][3] + b1;
                if (do_relu) {
                    e0 = fmaxf(e0, 0.f); e1 = fmaxf(e1, 0.f);
                    e2 = fmaxf(e2, 0.f); e3 = fmaxf(e3, 0.f);
                }
                p[mt][0][0] = fmaf(e0, w00, fmaf(e1, w10, p[mt][0][0]));
                p[mt][0][1] = fmaf(e0, w01, fmaf(e1, w11, p[mt][0][1]));
                p[mt][1][0] = fmaf(e2, w00, fmaf(e3, w10, p[mt][1][0]));
                p[mt][1][1] = fmaf(e2, w01, fmaf(e3, w11, p[mt][1][1]));
            }
        }
#pragma unroll
        for (int mt = 0; mt < 2; mt++)
#pragma unroll
            for (int h = 0; h < 2; h++)
#pragma unroll
                for (int o = 0; o < 2; o++) {
                    float v = p[mt][h][o];
                    v += __shfl_xor_sync(0xffffffffu, v, 1);
                    v += __shfl_xor_sync(0xffffffffu, v, 2);
                    p[mt][h][o] = v;
                }
        __syncthreads();
        if (t == 0) {
#pragma unroll
            for (int mt = 0; mt < 2; mt++)
#pragma unroll
                for (int h = 0; h < 2; h++) {
                    int row = wm * 32 + mt * 16 + q + h * 8;
                    red[wn][row][0] = p[mt][h][0];
                    red[wn][row][1] = p[mt][h][1];
                }
        }
        __syncthreads();
        {
            int row = tid >> 1, o = tid & 1;
            int grow = mbase + row;
            if (grow < M)
                outp[(size_t)grow * 2 + o] = red[0][row][o] + red[1][row][o] + bf2[o];
        }
    } else {
        // fp32 output (K2a/K2b -> AB)
#pragma unroll
        for (int mt = 0; mt < 2; mt++) {
#pragma unroll
            for (int nt = 0; nt < 8; nt++) {
                int row = mbase + wm * 32 + mt * 16 + q;
                int col = wn * 64 + nt * 8 + 2 * t;
                float v0 = acc[mt][nt][0];
                float v1 = acc[mt][nt][1];
                float v2 = acc[mt][nt][2];
                float v3 = acc[mt][nt][3];
                if (row < M)
                    *(float2*)(C + (size_t)row * ldc + col) = make_float2(v0, v1);
                if (row + 8 < M)
                    *(float2*)(C + (size_t)(row + 8) * ldc + col) = make_float2(v2, v3);
            }
        }
    }
#undef PK_ISSUE
}

// ---------------------------------------------------------------------------
// K3: E = mean_s relu(A[idx0] + B[idx1] + b_g1); writes E as packed hi/lo.
// ---------------------------------------------------------------------------
__global__ __launch_bounds__(256) void gather_mean_kernel(
    const float4* __restrict__ AB,
    const int* __restrict__ idx0, const int* __restrict__ idx1,
    const float* __restrict__ bg,
    uint32_t* __restrict__ Ehi, uint32_t* __restrict__ Elo)
{
    int gw   = (blockIdx.x * blockDim.x + threadIdx.x) >> 5;
    int lane = threadIdx.x & 31;
    if (gw >= L_NODES) return;

    float4 bg4 = ((const float4*)bg)[lane];
    float4 acc = make_float4(0.f, 0.f, 0.f, 0.f);
#pragma unroll
    for (int s = 0; s < NSAMP; s++) {
        int i0 = idx0[s * L_NODES + gw];
        int i1 = idx1[s * L_NODES + gw];
        float4 a = AB[(size_t)i0 * 64 + lane];
        float4 b = AB[(size_t)i1 * 64 + 32 + lane];
        acc.x += fmaxf(a.x + b.x + bg4.x, 0.f);
        acc.y += fmaxf(a.y + b.y + bg4.y, 0.f);
        acc.z += fmaxf(a.z + b.z + bg4.z, 0.f);
        acc.w += fmaxf(a.w + b.w + bg4.w, 0.f);
    }
    const float inv = 1.0f / (float)NSAMP;
    float m0 = acc.x * inv, m1 = acc.y * inv, m2 = acc.z * inv, m3 = acc.w * inv;
    unsigned short h0 = bfh(m0), h1 = bfh(m1), h2 = bfh(m2), h3 = bfh(m3);
    size_t base = (size_t)gw * 64 + 2 * lane;
    *(uint2*)&Ehi[base] = make_uint2(pack2(h0, h1), pack2(h2, h3));
    *(uint2*)&Elo[base] = make_uint2(
        pack2(bfh(m0 - bff(h0)), bfh(m1 - bff(h1))),
        pack2(bfh(m2 - bff(h2)), bfh(m3 - bff(h3))));
}

extern "C" void kernel_launch(void* const* d_in, const int* in_sizes, int n_in,
                              void* d_out, int out_size)
{
    const float* X    = (const float*)d_in[0];
    const float* W_h1 = (const float*)d_in[1];
    const float* b_h1 = (const float*)d_in[2];
    const float* W_g1 = (const float*)d_in[3];
    const float* b_g1 = (const float*)d_in[4];
    const float* W_f  = (const float*)d_in[5];
    const float* b_f  = (const float*)d_in[6];
    const int*   idx0 = (const int*)d_in[7];
    const int*   idx1 = (const int*)d_in[8];
    float* out = (float*)d_out;

    uint32_t *Hhi, *Hlo, *Ehi, *Elo, *Wh1h, *Wh1l, *Wg1h, *Wg1l;
    float* AB;
    cudaGetSymbolAddress((void**)&Hhi, g_Hhi);
    cudaGetSymbolAddress((void**)&Hlo, g_Hlo);
    cudaGetSymbolAddress((void**)&Ehi, g_Ehi);
    cudaGetSymbolAddress((void**)&Elo, g_Elo);
    cudaGetSymbolAddress((void**)&AB,  g_AB);
    cudaGetSymbolAddress((void**)&Wh1h, g_WPh1h);
    cudaGetSymbolAddress((void**)&Wh1l, g_WPh1l);
    cudaGetSymbolAddress((void**)&Wg1h, g_WPg1h);
    cudaGetSymbolAddress((void**)&Wg1l, g_WPg1l);

    const int MT = (L_NODES + 127) / 128;  // 782 tiles
    const int GW = (L_NODES * 32) / 256;   // 12500 blocks

    // P: pack weights
    prep_weights<<<64, 256>>>(W_h1, W_g1);
    // K1: Hpacked = relu(X @ W_h1 + b_h1)
    bgemm_f32<<<MT, 256>>>(X, 256, 256, Wh1h, Wh1l, b_h1, Hhi, Hlo, L_NODES, 1);
    // K2a: AB[:,0:128] = H @ Wtop
    bgemm_pk<<<MT, 256>>>(Hhi, Hlo, nullptr, nullptr, 128, 128, 64,
                          Wg1h, Wg1l, nullptr, AB, 256, L_NODES, 0,
                          nullptr, nullptr, nullptr);
    // K2b: AB[:,128:256] = H @ Wbot
    bgemm_pk<<<MT, 256>>>(Hhi, Hlo, nullptr, nullptr, 128, 128, 64,
                          Wg1h + 64 * 128, Wg1l + 64 * 128, nullptr,
                          AB + 128, 256, L_NODES, 0,
                          nullptr, nullptr, nullptr);
    // K3: Epacked = mean_s relu(A[idx0] + B[idx1] + b_g1)
    gather_mean_kernel<<<GW, 256>>>((const float4*)AB, idx0, idx1, b_g1, Ehi, Elo);
    // K4+K5: out = relu([H|E] @ W_g1 + b_g1) @ W_f + b_f
    bgemm_pk<<<MT, 256>>>(Hhi, Hlo, Ehi, Elo, 128, 256, 64,
                          Wg1h, Wg1l, b_g1, nullptr, 0, L_NODES, 1,
                          W_f, b_f, out);
}